// round 5
// baseline (speedup 1.0000x reference)
#include <cuda_runtime.h>
#include <cuda_fp16.h>

// Problem constants (fixed by the reference)
#define N_NODES 20000
#define N_EDGES 200000
#define N_SEG   16
#define EXTENT  32
#define N_PATHS 64
#define OP_SIZE (N_SEG * EXTENT)   // 512
#define EPB     4                  // edges per block (200000 % 4 == 0)

// Path metadata sorted by output segment (i3), built by prep kernel.
// meta.x = i1 tile byte offset in the half[pos][4] layout (= i1*EXTENT*EPB*2)
// meta.y = i2 tile byte offset, meta.z = coeff bits (f32).
__device__ int4 g_meta[N_PATHS];
__device__ int  g_seg_start[N_SEG + 1];

__global__ void prep_paths_kernel(const int* __restrict__ path_indices,
                                  const float* __restrict__ path_coeffs) {
    if (threadIdx.x != 0 || blockIdx.x != 0) return;
    int cnt[N_SEG];
#pragma unroll
    for (int s = 0; s < N_SEG; s++) cnt[s] = 0;
    for (int p = 0; p < N_PATHS; p++) cnt[path_indices[p * 3 + 2]]++;
    int start[N_SEG + 1];
    start[0] = 0;
#pragma unroll
    for (int s = 0; s < N_SEG; s++) start[s + 1] = start[s] + cnt[s];
    for (int s = 0; s <= N_SEG; s++) g_seg_start[s] = start[s];
    int pos[N_SEG];
#pragma unroll
    for (int s = 0; s < N_SEG; s++) pos[s] = start[s];
    for (int p = 0; p < N_PATHS; p++) {
        int s   = path_indices[p * 3 + 2];
        int idx = pos[s]++;
        int4 m;
        m.x = path_indices[p * 3 + 0] * (EXTENT * EPB * 2);  // bytes
        m.y = path_indices[p * 3 + 1] * (EXTENT * EPB * 2);
        m.z = __float_as_int(path_coeffs[p]);
        m.w = 0;
        g_meta[idx] = m;
    }
}

// 4 edges per block, f16 tiles transposed to [pos][edge] so one LDS.64 fetches
// the 4 edges' values for a (seg,lane) position. 512 threads = 16 seg x 32 ext.
__global__ __launch_bounds__(OP_SIZE, 3)
void seg_poly_kernel(const float* __restrict__ x_nodes,
                     const float* __restrict__ x_edges,
                     const int* __restrict__ src,
                     const int* __restrict__ dst,
                     float* __restrict__ out) {
    __shared__ __align__(16) __half s_x1[OP_SIZE * EPB];  // [512 pos][4 edges], 4 KB
    __shared__ __align__(16) __half s_x2[OP_SIZE * EPB];  // 4 KB
    __shared__ int4 s_meta[N_PATHS];
    __shared__ int  s_start[N_SEG + 1];
    __shared__ int  s_dst[EPB];

    const int e0 = blockIdx.x * EPB;
    const int t  = threadIdx.x;

    // Stage x_edges: thread t owns position t; gather its value from all 4
    // edges (each LDG coalesced in-warp), convert to f16, one STS.64.
    {
        float v0 = x_edges[(size_t)(e0 + 0) * OP_SIZE + t];
        float v1 = x_edges[(size_t)(e0 + 1) * OP_SIZE + t];
        float v2 = x_edges[(size_t)(e0 + 2) * OP_SIZE + t];
        float v3 = x_edges[(size_t)(e0 + 3) * OP_SIZE + t];
        __half2 h01 = __floats2half2_rn(v0, v1);
        __half2 h23 = __floats2half2_rn(v2, v3);
        uint2 pk;
        pk.x = *(const unsigned*)&h01;
        pk.y = *(const unsigned*)&h23;
        ((uint2*)s_x2)[t] = pk;   // addr = t*8 -> conflict-free
    }
    // Stage x_nodes rows src[e0..e0+3] the same way (uniform src loads hit L1).
    {
        const int r0 = src[e0 + 0];
        const int r1 = src[e0 + 1];
        const int r2 = src[e0 + 2];
        const int r3 = src[e0 + 3];
        float v0 = x_nodes[(size_t)r0 * OP_SIZE + t];
        float v1 = x_nodes[(size_t)r1 * OP_SIZE + t];
        float v2 = x_nodes[(size_t)r2 * OP_SIZE + t];
        float v3 = x_nodes[(size_t)r3 * OP_SIZE + t];
        __half2 h01 = __floats2half2_rn(v0, v1);
        __half2 h23 = __floats2half2_rn(v2, v3);
        uint2 pk;
        pk.x = *(const unsigned*)&h01;
        pk.y = *(const unsigned*)&h23;
        ((uint2*)s_x1)[t] = pk;
    }

    if (t < N_PATHS) s_meta[t] = g_meta[t];
    if (t <= N_SEG)  s_start[t] = g_seg_start[t];
    if (t < EPB)     s_dst[t] = dst[e0 + t];
    __syncthreads();

    const int lane = t & 31;
    const int j0 = s_start[t >> 5];
    const int j1 = s_start[(t >> 5) + 1];

    const char* b1 = (const char*)s_x1 + lane * (EPB * 2);
    const char* b2 = (const char*)s_x2 + lane * (EPB * 2);

    float a0 = 0.f, a1 = 0.f, a2 = 0.f, a3 = 0.f;

    // Most segments have <= 4 paths: predicated unrolled batch, then rare spill.
#pragma unroll
    for (int u = 0; u < 4; u++) {
        const int j = j0 + u;
        if (j < j1) {
            const int4 m = s_meta[j];
            const float c = __int_as_float(m.z);
            const uint2 v1 = *(const uint2*)(b1 + m.x);   // LDS.64: edges 0-3 (x1)
            const uint2 v2 = *(const uint2*)(b2 + m.y);   // LDS.64: edges 0-3 (x2)
            const float2 x1lo = __half22float2(*(const __half2*)&v1.x);
            const float2 x1hi = __half22float2(*(const __half2*)&v1.y);
            const float2 x2lo = __half22float2(*(const __half2*)&v2.x);
            const float2 x2hi = __half22float2(*(const __half2*)&v2.y);
            a0 = fmaf(c * x1lo.x, x2lo.x, a0);
            a1 = fmaf(c * x1lo.y, x2lo.y, a1);
            a2 = fmaf(c * x1hi.x, x2hi.x, a2);
            a3 = fmaf(c * x1hi.y, x2hi.y, a3);
        }
    }
    for (int j = j0 + 4; j < j1; j++) {
        const int4 m = s_meta[j];
        const float c = __int_as_float(m.z);
        const uint2 v1 = *(const uint2*)(b1 + m.x);
        const uint2 v2 = *(const uint2*)(b2 + m.y);
        const float2 x1lo = __half22float2(*(const __half2*)&v1.x);
        const float2 x1hi = __half22float2(*(const __half2*)&v1.y);
        const float2 x2lo = __half22float2(*(const __half2*)&v2.x);
        const float2 x2hi = __half22float2(*(const __half2*)&v2.y);
        a0 = fmaf(c * x1lo.x, x2lo.x, a0);
        a1 = fmaf(c * x1lo.y, x2lo.y, a1);
        a2 = fmaf(c * x1hi.x, x2hi.x, a2);
        a3 = fmaf(c * x1hi.y, x2hi.y, a3);
    }

    if (j1 > j0) {
        // Unused return -> no-return global reduction, coalesced 128B per warp.
        atomicAdd(&out[(size_t)s_dst[0] * OP_SIZE + t], a0);
        atomicAdd(&out[(size_t)s_dst[1] * OP_SIZE + t], a1);
        atomicAdd(&out[(size_t)s_dst[2] * OP_SIZE + t], a2);
        atomicAdd(&out[(size_t)s_dst[3] * OP_SIZE + t], a3);
    }
    // Segments with no paths contribute exactly 0 -> output stays at memset 0.
}

extern "C" void kernel_launch(void* const* d_in, const int* in_sizes, int n_in,
                              void* d_out, int out_size) {
    const float* x_nodes      = (const float*)d_in[0];
    const float* x_edges      = (const float*)d_in[1];
    const float* path_coeffs  = (const float*)d_in[2];
    const int*   src          = (const int*)d_in[3];
    const int*   dst          = (const int*)d_in[4];
    const int*   path_indices = (const int*)d_in[5];
    float* out = (float*)d_out;

    // Output is poisoned 0xAA by the harness; zero it (graph-capturable).
    cudaMemsetAsync(out, 0, (size_t)N_NODES * OP_SIZE * sizeof(float));

    prep_paths_kernel<<<1, 32>>>(path_indices, path_coeffs);

    seg_poly_kernel<<<N_EDGES / EPB, OP_SIZE>>>(x_nodes, x_edges, src, dst, out);
}

// round 7
// speedup vs baseline: 1.4646x; 1.4646x over previous
#include <cuda_runtime.h>
#include <cuda_fp16.h>

// Problem constants (fixed by the reference)
#define N_NODES 20000
#define N_EDGES 200000
#define N_SEG   16
#define EXTENT  32
#define N_PATHS 64
#define OP_SIZE (N_SEG * EXTENT)   // 512
#define EPB     8                  // edges per block (200000 % 8 == 0)

// Path metadata sorted by output segment (i3), built by prep kernel.
// meta.x = i1 tile byte offset in half[pos][EPB] layout (= i1*EXTENT*EPB*2)
// meta.y = i2 tile byte offset, meta.z = coeff bits (f32).
__device__ int4 g_meta[N_PATHS];
__device__ int  g_seg_start[N_SEG + 1];

__global__ void prep_paths_kernel(const int* __restrict__ path_indices,
                                  const float* __restrict__ path_coeffs) {
    if (threadIdx.x != 0 || blockIdx.x != 0) return;
    int cnt[N_SEG];
#pragma unroll
    for (int s = 0; s < N_SEG; s++) cnt[s] = 0;
    for (int p = 0; p < N_PATHS; p++) cnt[path_indices[p * 3 + 2]]++;
    int start[N_SEG + 1];
    start[0] = 0;
#pragma unroll
    for (int s = 0; s < N_SEG; s++) start[s + 1] = start[s] + cnt[s];
    for (int s = 0; s <= N_SEG; s++) g_seg_start[s] = start[s];
    int pos[N_SEG];
#pragma unroll
    for (int s = 0; s < N_SEG; s++) pos[s] = start[s];
    for (int p = 0; p < N_PATHS; p++) {
        int s   = path_indices[p * 3 + 2];
        int idx = pos[s]++;
        int4 m;
        m.x = path_indices[p * 3 + 0] * (EXTENT * EPB * 2);  // bytes
        m.y = path_indices[p * 3 + 1] * (EXTENT * EPB * 2);
        m.z = __float_as_int(path_coeffs[p]);
        m.w = 0;
        g_meta[idx] = m;
    }
}

// 8 edges per block, f16 tiles transposed to [pos][edge]: one LDS.128 fetches
// all 8 edges' values for a (seg,lane) position. 512 threads = 16 seg x 32 ext.
// Products in half2 (HMUL2), accumulate in f32 with the coeff (8 indep chains).
__global__ __launch_bounds__(OP_SIZE, 3)
void seg_poly_kernel(const float* __restrict__ x_nodes,
                     const float* __restrict__ x_edges,
                     const int* __restrict__ src,
                     const int* __restrict__ dst,
                     float* __restrict__ out) {
    __shared__ __align__(16) __half s_x1[OP_SIZE * EPB];  // [512 pos][8 edges], 8 KB
    __shared__ __align__(16) __half s_x2[OP_SIZE * EPB];  // 8 KB
    __shared__ int4 s_meta[N_PATHS];
    __shared__ int  s_start[N_SEG + 1];
    __shared__ int  s_dst[EPB];

    const int e0 = blockIdx.x * EPB;
    const int t  = threadIdx.x;

    // Stage x_edges: thread t owns position t; gather from all 8 edges
    // (each LDG coalesced in-warp, 8 independent loads -> MLP 8), one STS.128.
    {
        const float* base = x_edges + (size_t)e0 * OP_SIZE + t;
        float v0 = base[0 * OP_SIZE], v1 = base[1 * OP_SIZE];
        float v2 = base[2 * OP_SIZE], v3 = base[3 * OP_SIZE];
        float v4 = base[4 * OP_SIZE], v5 = base[5 * OP_SIZE];
        float v6 = base[6 * OP_SIZE], v7 = base[7 * OP_SIZE];
        __half2 h0 = __floats2half2_rn(v0, v1);
        __half2 h1 = __floats2half2_rn(v2, v3);
        __half2 h2 = __floats2half2_rn(v4, v5);
        __half2 h3 = __floats2half2_rn(v6, v7);
        uint4 pk;
        pk.x = *(const unsigned*)&h0; pk.y = *(const unsigned*)&h1;
        pk.z = *(const unsigned*)&h2; pk.w = *(const unsigned*)&h3;
        ((uint4*)s_x2)[t] = pk;   // addr = t*16 -> conflict-free
    }
    // Stage x_nodes rows src[e0..e0+7] the same way (uniform src loads hit L1).
    {
        int r[EPB];
#pragma unroll
        for (int e = 0; e < EPB; e++) r[e] = src[e0 + e];
        float v[EPB];
#pragma unroll
        for (int e = 0; e < EPB; e++)
            v[e] = x_nodes[(size_t)r[e] * OP_SIZE + t];
        __half2 h0 = __floats2half2_rn(v[0], v[1]);
        __half2 h1 = __floats2half2_rn(v[2], v[3]);
        __half2 h2 = __floats2half2_rn(v[4], v[5]);
        __half2 h3 = __floats2half2_rn(v[6], v[7]);
        uint4 pk;
        pk.x = *(const unsigned*)&h0; pk.y = *(const unsigned*)&h1;
        pk.z = *(const unsigned*)&h2; pk.w = *(const unsigned*)&h3;
        ((uint4*)s_x1)[t] = pk;
    }

    if (t < N_PATHS) s_meta[t] = g_meta[t];
    if (t <= N_SEG)  s_start[t] = g_seg_start[t];
    if (t < EPB)     s_dst[t] = dst[e0 + t];
    __syncthreads();

    const int lane = t & 31;
    const int j0 = s_start[t >> 5];
    const int j1 = s_start[(t >> 5) + 1];

    const char* b1 = (const char*)s_x1 + lane * (EPB * 2);
    const char* b2 = (const char*)s_x2 + lane * (EPB * 2);

    float a0 = 0.f, a1 = 0.f, a2 = 0.f, a3 = 0.f;
    float a4 = 0.f, a5 = 0.f, a6 = 0.f, a7 = 0.f;

    for (int j = j0; j < j1; j++) {
        const int4 m = s_meta[j];                       // LDS.128, warp-uniform
        const float c = __int_as_float(m.z);
        const uint4 w1 = *(const uint4*)(b1 + m.x);     // LDS.128: 8 edges (x1)
        const uint4 w2 = *(const uint4*)(b2 + m.y);     // LDS.128: 8 edges (x2)
        const __half2 p0 = __hmul2(*(const __half2*)&w1.x, *(const __half2*)&w2.x);
        const __half2 p1 = __hmul2(*(const __half2*)&w1.y, *(const __half2*)&w2.y);
        const __half2 p2 = __hmul2(*(const __half2*)&w1.z, *(const __half2*)&w2.z);
        const __half2 p3 = __hmul2(*(const __half2*)&w1.w, *(const __half2*)&w2.w);
        const float2 f0 = __half22float2(p0);
        const float2 f1 = __half22float2(p1);
        const float2 f2 = __half22float2(p2);
        const float2 f3 = __half22float2(p3);
        a0 = fmaf(c, f0.x, a0);  a1 = fmaf(c, f0.y, a1);
        a2 = fmaf(c, f1.x, a2);  a3 = fmaf(c, f1.y, a3);
        a4 = fmaf(c, f2.x, a4);  a5 = fmaf(c, f2.y, a5);
        a6 = fmaf(c, f3.x, a6);  a7 = fmaf(c, f3.y, a7);
    }

    if (j1 > j0) {
        // Unused return -> no-return global reduction, coalesced 128B per warp.
        atomicAdd(&out[(size_t)s_dst[0] * OP_SIZE + t], a0);
        atomicAdd(&out[(size_t)s_dst[1] * OP_SIZE + t], a1);
        atomicAdd(&out[(size_t)s_dst[2] * OP_SIZE + t], a2);
        atomicAdd(&out[(size_t)s_dst[3] * OP_SIZE + t], a3);
        atomicAdd(&out[(size_t)s_dst[4] * OP_SIZE + t], a4);
        atomicAdd(&out[(size_t)s_dst[5] * OP_SIZE + t], a5);
        atomicAdd(&out[(size_t)s_dst[6] * OP_SIZE + t], a6);
        atomicAdd(&out[(size_t)s_dst[7] * OP_SIZE + t], a7);
    }
    // Segments with no paths contribute exactly 0 -> output stays at memset 0.
}

extern "C" void kernel_launch(void* const* d_in, const int* in_sizes, int n_in,
                              void* d_out, int out_size) {
    const float* x_nodes      = (const float*)d_in[0];
    const float* x_edges      = (const float*)d_in[1];
    const float* path_coeffs  = (const float*)d_in[2];
    const int*   src          = (const int*)d_in[3];
    const int*   dst          = (const int*)d_in[4];
    const int*   path_indices = (const int*)d_in[5];
    float* out = (float*)d_out;

    // Output is poisoned 0xAA by the harness; zero it (graph-capturable).
    cudaMemsetAsync(out, 0, (size_t)N_NODES * OP_SIZE * sizeof(float));

    prep_paths_kernel<<<1, 32>>>(path_indices, path_coeffs);

    seg_poly_kernel<<<N_EDGES / EPB, OP_SIZE>>>(x_nodes, x_edges, src, dst, out);
}